// round 6
// baseline (speedup 1.0000x reference)
#include <cuda_runtime.h>
#include <cuda_bf16.h>

#define N_NODES 100000
#define N_EDGES 1600000
#define IN_DIM  16
#define HID     128
#define LN_EPS  1e-5f

// ---------------- scratch (no allocation allowed) ----------------
__device__ float g_dis[N_NODES];
__device__ int   g_cnt[N_NODES];
__device__ int   g_rowptr[N_NODES + 1];
__device__ int   g_cursor[N_NODES];
__device__ int   g_partial[128];
__device__ int   g_col[N_EDGES];
__device__ float g_w[N_EDGES];
__device__ float g_m[(size_t)N_NODES * HID];
__device__ float g_h0[(size_t)N_NODES * HID];
__device__ float g_h1[(size_t)N_NODES * HID];
__device__ float g_Wc[IN_DIM * HID];   // W_in @ W_conv[0]
__device__ float g_bc[HID];            // b_in @ W_conv[0]
__device__ int   g_stride;  // 1 = int32 storage, 2 = int64 storage

__device__ __forceinline__ float* buf_sel(int s) {
    return (s == 0) ? g_h0 : g_h1;
}

// ---------------- dtype detection ----------------
__global__ void k_detect(const int* __restrict__ ei_w) {
    if (threadIdx.x == 0) {
        bool all_zero = true;
        for (int i = 0; i < 32; i++)
            if (ei_w[2 * i + 1] != 0) { all_zero = false; break; }
        g_stride = all_zero ? 2 : 1;
    }
}

// ---------------- graph preprocessing ----------------
__global__ void k_zero_cnt() {
    int i = blockIdx.x * blockDim.x + threadIdx.x;
    if (i < N_NODES) g_cnt[i] = 0;
}

__global__ void k_count(const int* __restrict__ ei_w) {
    int e = blockIdx.x * blockDim.x + threadIdx.x;
    if (e >= N_EDGES) return;
    int st = g_stride;
    int d = ei_w[(size_t)N_EDGES * st + (size_t)e * st];
    if ((unsigned)d < N_NODES) atomicAdd(&g_cnt[d], 1);
}

__global__ void k_deg() {
    int i = blockIdx.x * blockDim.x + threadIdx.x;
    if (i < N_NODES) g_dis[i] = rsqrtf((float)(g_cnt[i] + 1));  // +1 self loop
}

// exclusive scan of g_cnt -> g_rowptr (block-local) + block totals
__global__ void k_scan1() {
    __shared__ int warp_sums[32];
    int tid = threadIdx.x;
    int gid = blockIdx.x * 1024 + tid;
    int v = (gid < N_NODES) ? g_cnt[gid] : 0;
    int lane = tid & 31, wid = tid >> 5;
    int x = v;
    #pragma unroll
    for (int o = 1; o < 32; o <<= 1) {
        int y = __shfl_up_sync(0xFFFFFFFFu, x, o);
        if (lane >= o) x += y;
    }
    if (lane == 31) warp_sums[wid] = x;
    __syncthreads();
    if (wid == 0) {
        int s = warp_sums[lane];
        #pragma unroll
        for (int o = 1; o < 32; o <<= 1) {
            int y = __shfl_up_sync(0xFFFFFFFFu, s, o);
            if (lane >= o) s += y;
        }
        warp_sums[lane] = s;
    }
    __syncthreads();
    int base = (wid > 0) ? warp_sums[wid - 1] : 0;
    if (gid < N_NODES) g_rowptr[gid] = base + x - v;  // exclusive
    if (tid == 1023) g_partial[blockIdx.x] = base + x;  // block total
}

__global__ void k_scan2(int nblocks) {
    if (threadIdx.x == 0 && blockIdx.x == 0) {
        int acc = 0;
        for (int i = 0; i < nblocks; i++) {
            int t = g_partial[i];
            g_partial[i] = acc;
            acc += t;
        }
    }
}

__global__ void k_scan3() {
    int i = blockIdx.x * blockDim.x + threadIdx.x;
    if (i < N_NODES) {
        int rp = g_rowptr[i] + g_partial[i >> 10];
        g_rowptr[i] = rp;
        g_cursor[i] = rp;
    }
    if (i == 0) g_rowptr[N_NODES] = N_EDGES;
}

__global__ void k_scatter(const int* __restrict__ ei_w) {
    int e = blockIdx.x * blockDim.x + threadIdx.x;
    if (e >= N_EDGES) return;
    int st = g_stride;
    int s = ei_w[(size_t)e * st];
    int d = ei_w[(size_t)N_EDGES * st + (size_t)e * st];
    if ((unsigned)s >= N_NODES || (unsigned)d >= N_NODES) return;
    int pos = atomicAdd(&g_cursor[d], 1);
    if ((unsigned)pos < N_EDGES) {
        g_col[pos] = s;
        g_w[pos] = g_dis[s] * g_dis[d];
    }
}

// ---------------- combined weight: Wc = W_in @ W0, bc = b_in @ W0 ----------------
__global__ void k_combine(const float* __restrict__ Win,
                          const float* __restrict__ bin,
                          const float* __restrict__ W0) {
    int c = threadIdx.x;  // 128 threads, one output column each
    float acc[IN_DIM];
    #pragma unroll
    for (int k = 0; k < IN_DIM; k++) acc[k] = 0.f;
    float bacc = 0.f;
    for (int j = 0; j < HID; j++) {
        float w = W0[j * HID + c];
        bacc += bin[j] * w;
        #pragma unroll
        for (int k = 0; k < IN_DIM; k++) acc[k] += Win[k * HID + j] * w;
    }
    #pragma unroll
    for (int k = 0; k < IN_DIM; k++) g_Wc[k * HID + c] = acc[k];
    g_bc[c] = bacc;
}

// -------- layer-0 fused transform: g_m = x @ Wc + bc  (K=16) --------
// Warp-per-node, W slice register-resident (16 float4 = 64 regs per lane).
#define F0_BLOCKS 1024
__global__ void __launch_bounds__(256) k_fused0(const float* __restrict__ x) {
    int tid = threadIdx.x;
    int lane = tid & 31;
    int warp_gid = (blockIdx.x * 256 + tid) >> 5;
    const int total_warps = F0_BLOCKS * 8;
    int c4 = lane * 4;

    float4 Wr[IN_DIM];
    #pragma unroll
    for (int k = 0; k < IN_DIM; k++)
        Wr[k] = *(const float4*)&g_Wc[k * HID + c4];
    float4 bs = *(const float4*)&g_bc[c4];

    for (int n = warp_gid; n < N_NODES; n += total_warps) {
        const float4* xr = (const float4*)(x + (size_t)n * IN_DIM);
        float4 xv0 = xr[0], xv1 = xr[1], xv2 = xr[2], xv3 = xr[3];
        float xk[IN_DIM] = {xv0.x, xv0.y, xv0.z, xv0.w,
                            xv1.x, xv1.y, xv1.z, xv1.w,
                            xv2.x, xv2.y, xv2.z, xv2.w,
                            xv3.x, xv3.y, xv3.z, xv3.w};
        float4 acc = bs;
        #pragma unroll
        for (int k = 0; k < IN_DIM; k++) {
            acc.x += xk[k] * Wr[k].x;
            acc.y += xk[k] * Wr[k].y;
            acc.z += xk[k] * Wr[k].z;
            acc.w += xk[k] * Wr[k].w;
        }
        *(float4*)&g_m[(size_t)n * HID + c4] = acc;
    }
}

// ---------------- GEMM: g_m = h(sel) @ W  (100000 x 128 x 128) ----------------
__global__ void __launch_bounds__(256) k_gemm(int hsel, const float* __restrict__ W) {
    extern __shared__ float Ws[];  // HID*HID floats = 64KB
    int tid = threadIdx.x;
    for (int i = tid; i < (HID * HID) / 4; i += 256)
        ((float4*)Ws)[i] = ((const float4*)W)[i];
    __syncthreads();

    const float* __restrict__ h = buf_sel(hsel);

    int row0 = blockIdx.x * 64 + (tid >> 5) * 8;
    int c4 = (tid & 31) * 4;

    const float* hp[8];
    #pragma unroll
    for (int r = 0; r < 8; r++) {
        int row = row0 + r;
        if (row >= N_NODES) row = N_NODES - 1;
        hp[r] = h + (size_t)row * HID;
    }

    float4 acc[8];
    #pragma unroll
    for (int r = 0; r < 8; r++) acc[r] = make_float4(0.f, 0.f, 0.f, 0.f);

    for (int k = 0; k < HID; k += 4) {
        float4 wv0 = *(const float4*)&Ws[(k + 0) * HID + c4];
        float4 wv1 = *(const float4*)&Ws[(k + 1) * HID + c4];
        float4 wv2 = *(const float4*)&Ws[(k + 2) * HID + c4];
        float4 wv3 = *(const float4*)&Ws[(k + 3) * HID + c4];
        #pragma unroll
        for (int r = 0; r < 8; r++) {
            float4 hv = *(const float4*)(hp[r] + k);
            acc[r].x += hv.x * wv0.x + hv.y * wv1.x + hv.z * wv2.x + hv.w * wv3.x;
            acc[r].y += hv.x * wv0.y + hv.y * wv1.y + hv.z * wv2.y + hv.w * wv3.y;
            acc[r].z += hv.x * wv0.z + hv.y * wv1.z + hv.z * wv2.z + hv.w * wv3.z;
            acc[r].w += hv.x * wv0.w + hv.y * wv1.w + hv.z * wv2.w + hv.w * wv3.w;
        }
    }
    #pragma unroll
    for (int r = 0; r < 8; r++) {
        int row = row0 + r;
        if (row < N_NODES)
            *(float4*)&g_m[(size_t)row * HID + c4] = acc[r];
    }
}

// -------- aggregation + bias + LayerNorm + ReLU + residual --------
__global__ void k_agg(const float* __restrict__ bconv,
                      const float* __restrict__ gamma,
                      const float* __restrict__ beta,
                      int prevsel, int outsel, float* out_ext) {
    int warp = (blockIdx.x * blockDim.x + threadIdx.x) >> 5;
    int lane = threadIdx.x & 31;
    if (warp >= N_NODES) return;
    int i = warp;

    float di = g_dis[i];
    float sc = di * di;
    float4 acc = *(const float4*)&g_m[(size_t)i * HID + lane * 4];
    acc.x *= sc; acc.y *= sc; acc.z *= sc; acc.w *= sc;
    float4 acc2 = make_float4(0.f, 0.f, 0.f, 0.f);

    int e0 = g_rowptr[i], e1 = g_rowptr[i + 1];
    int e = e0;
    for (; e + 4 <= e1; e += 4) {
        int s0 = g_col[e],     s1 = g_col[e + 1];
        int s2 = g_col[e + 2], s3 = g_col[e + 3];
        float w0 = g_w[e],     w1 = g_w[e + 1];
        float w2 = g_w[e + 2], w3 = g_w[e + 3];
        float4 m0 = *(const float4*)&g_m[(size_t)s0 * HID + lane * 4];
        float4 m1 = *(const float4*)&g_m[(size_t)s1 * HID + lane * 4];
        float4 m2 = *(const float4*)&g_m[(size_t)s2 * HID + lane * 4];
        float4 m3 = *(const float4*)&g_m[(size_t)s3 * HID + lane * 4];
        acc.x  += m0.x * w0 + m1.x * w1;
        acc.y  += m0.y * w0 + m1.y * w1;
        acc.z  += m0.z * w0 + m1.z * w1;
        acc.w  += m0.w * w0 + m1.w * w1;
        acc2.x += m2.x * w2 + m3.x * w3;
        acc2.y += m2.y * w2 + m3.y * w3;
        acc2.z += m2.z * w2 + m3.z * w3;
        acc2.w += m2.w * w2 + m3.w * w3;
    }
    for (; e < e1; e++) {
        int s0 = g_col[e];
        float w0 = g_w[e];
        float4 m0 = *(const float4*)&g_m[(size_t)s0 * HID + lane * 4];
        acc.x += m0.x * w0;
        acc.y += m0.y * w0;
        acc.z += m0.z * w0;
        acc.w += m0.w * w0;
    }
    acc.x += acc2.x; acc.y += acc2.y; acc.z += acc2.z; acc.w += acc2.w;

    float4 bv = *(const float4*)&bconv[lane * 4];
    acc.x += bv.x; acc.y += bv.y; acc.z += bv.z; acc.w += bv.w;

    // LayerNorm over 128 values held as 4/lane within the warp
    float sum = acc.x + acc.y + acc.z + acc.w;
    float sumsq = acc.x * acc.x + acc.y * acc.y + acc.z * acc.z + acc.w * acc.w;
    #pragma unroll
    for (int o = 16; o >= 1; o >>= 1) {
        sum += __shfl_xor_sync(0xFFFFFFFFu, sum, o);
        sumsq += __shfl_xor_sync(0xFFFFFFFFu, sumsq, o);
    }
    float mu = sum * (1.0f / HID);
    float var = sumsq * (1.0f / HID) - mu * mu;
    float inv = rsqrtf(var + LN_EPS);

    float4 gv = *(const float4*)&gamma[lane * 4];
    float4 btv = *(const float4*)&beta[lane * 4];
    float4 o4;
    o4.x = fmaxf((acc.x - mu) * inv * gv.x + btv.x, 0.f);
    o4.y = fmaxf((acc.y - mu) * inv * gv.y + btv.y, 0.f);
    o4.z = fmaxf((acc.z - mu) * inv * gv.z + btv.z, 0.f);
    o4.w = fmaxf((acc.w - mu) * inv * gv.w + btv.w, 0.f);

    if (prevsel >= 0) {
        const float* hprev = buf_sel(prevsel);
        float4 hp = *(const float4*)&hprev[(size_t)i * HID + lane * 4];
        o4.x += hp.x; o4.y += hp.y; o4.z += hp.z; o4.w += hp.w;
    }

    float* out = (outsel == 2) ? out_ext : buf_sel(outsel);
    *(float4*)&out[(size_t)i * HID + lane * 4] = o4;
}

// ---------------- launch ----------------
extern "C" void kernel_launch(void* const* d_in, const int* in_sizes, int n_in,
                              void* d_out, int out_size) {
    const float* x     = (const float*)d_in[0];
    const int*   ei_w  = (const int*)d_in[1];   // edge_index words (int32 view)
    const float* Win   = (const float*)d_in[2];
    const float* bin   = (const float*)d_in[3];
    const float* Wconv = (const float*)d_in[4];  // [3,128,128]
    const float* bconv = (const float*)d_in[5];  // [3,128]
    const float* gamma = (const float*)d_in[6];  // [3,128]
    const float* beta  = (const float*)d_in[7];  // [3,128]
    float* out = (float*)d_out;

    cudaFuncSetAttribute(k_gemm, cudaFuncAttributeMaxDynamicSharedMemorySize,
                         HID * HID * sizeof(float));

    const int NODE_BLOCKS = (N_NODES + 255) / 256;
    const int EDGE_BLOCKS = (N_EDGES + 255) / 256;
    const int SCAN_BLOCKS = (N_NODES + 1023) / 1024;

    // Profiled launch slot is index 3 -> k_fused0 (verify the rewrite).
    k_combine<<<1, HID>>>(Win, bin, Wconv + 0 * HID * HID);   // 0
    k_detect<<<1, 32>>>(ei_w);                                 // 1
    k_zero_cnt<<<NODE_BLOCKS, 256>>>();                        // 2
    k_fused0<<<F0_BLOCKS, 256>>>(x);                           // 3 <- profiled
    k_count<<<EDGE_BLOCKS, 256>>>(ei_w);                       // 4
    k_deg<<<NODE_BLOCKS, 256>>>();                             // 5
    k_scan1<<<SCAN_BLOCKS, 1024>>>();                          // 6
    k_scan2<<<1, 32>>>(SCAN_BLOCKS);                           // 7
    k_scan3<<<NODE_BLOCKS, 256>>>();                           // 8
    k_scatter<<<EDGE_BLOCKS, 256>>>(ei_w);                     // 9

    const int GEMM_BLOCKS = (N_NODES + 63) / 64;
    const int AGG_BLOCKS = (N_NODES * 32 + 255) / 256;
    const size_t WSM = HID * HID * sizeof(float);

    // layer 0 agg: -> h1 (no residual)
    k_agg<<<AGG_BLOCKS, 256>>>(bconv + 0 * HID, gamma + 0 * HID, beta + 0 * HID,
                               -1, 1, nullptr);
    // layer 1: h1 -> h0 (+ residual h1)
    k_gemm<<<GEMM_BLOCKS, 256, WSM>>>(1, Wconv + 1 * HID * HID);
    k_agg<<<AGG_BLOCKS, 256>>>(bconv + 1 * HID, gamma + 1 * HID, beta + 1 * HID,
                               1, 0, nullptr);
    // layer 2: h0 -> out (+ residual h0)
    k_gemm<<<GEMM_BLOCKS, 256, WSM>>>(0, Wconv + 2 * HID * HID);
    k_agg<<<AGG_BLOCKS, 256>>>(bconv + 2 * HID, gamma + 2 * HID, beta + 2 * HID,
                               0, 2, out);
}

// round 7
// speedup vs baseline: 1.1106x; 1.1106x over previous
#include <cuda_runtime.h>
#include <cuda_bf16.h>

#define N_NODES 100000
#define N_EDGES 1600000
#define IN_DIM  16
#define HID     128
#define LN_EPS  1e-5f

// ---------------- scratch (no allocation allowed) ----------------
__device__ float g_dis[N_NODES];
__device__ int   g_cnt[N_NODES];
__device__ int   g_rowptr[N_NODES + 1];
__device__ int   g_cursor[N_NODES];
__device__ int   g_partial[128];
__device__ int   g_col[N_EDGES];
__device__ float g_w[N_EDGES];
__device__ float g_m[(size_t)N_NODES * HID];
__device__ float g_h0[(size_t)N_NODES * HID];
__device__ float g_h1[(size_t)N_NODES * HID];
__device__ float g_Wc[IN_DIM * HID];   // W_in @ W_conv[0]
__device__ float g_bc[HID];            // b_in @ W_conv[0]
__device__ int   g_stride;  // 1 = int32 storage, 2 = int64 storage

__device__ __forceinline__ float* buf_sel(int s) {
    return (s == 0) ? g_h0 : g_h1;
}

// ---------------- dtype detection ----------------
__global__ void k_detect(const int* __restrict__ ei_w) {
    if (threadIdx.x == 0) {
        bool all_zero = true;
        for (int i = 0; i < 32; i++)
            if (ei_w[2 * i + 1] != 0) { all_zero = false; break; }
        g_stride = all_zero ? 2 : 1;
    }
}

// ---------------- graph preprocessing ----------------
__global__ void k_zero_cnt() {
    int i = blockIdx.x * blockDim.x + threadIdx.x;
    if (i < N_NODES) g_cnt[i] = 0;
}

__global__ void k_count(const int* __restrict__ ei_w) {
    int e = blockIdx.x * blockDim.x + threadIdx.x;
    if (e >= N_EDGES) return;
    int st = g_stride;
    int d = ei_w[(size_t)N_EDGES * st + (size_t)e * st];
    if ((unsigned)d < N_NODES) atomicAdd(&g_cnt[d], 1);
}

__global__ void k_deg() {
    int i = blockIdx.x * blockDim.x + threadIdx.x;
    if (i < N_NODES) g_dis[i] = rsqrtf((float)(g_cnt[i] + 1));  // +1 self loop
}

// exclusive scan of g_cnt -> g_rowptr (block-local) + block totals
__global__ void k_scan1() {
    __shared__ int warp_sums[32];
    int tid = threadIdx.x;
    int gid = blockIdx.x * 1024 + tid;
    int v = (gid < N_NODES) ? g_cnt[gid] : 0;
    int lane = tid & 31, wid = tid >> 5;
    int x = v;
    #pragma unroll
    for (int o = 1; o < 32; o <<= 1) {
        int y = __shfl_up_sync(0xFFFFFFFFu, x, o);
        if (lane >= o) x += y;
    }
    if (lane == 31) warp_sums[wid] = x;
    __syncthreads();
    if (wid == 0) {
        int s = warp_sums[lane];
        #pragma unroll
        for (int o = 1; o < 32; o <<= 1) {
            int y = __shfl_up_sync(0xFFFFFFFFu, s, o);
            if (lane >= o) s += y;
        }
        warp_sums[lane] = s;
    }
    __syncthreads();
    int base = (wid > 0) ? warp_sums[wid - 1] : 0;
    if (gid < N_NODES) g_rowptr[gid] = base + x - v;  // exclusive
    if (tid == 1023) g_partial[blockIdx.x] = base + x;  // block total
}

__global__ void k_scan2(int nblocks) {
    if (threadIdx.x == 0 && blockIdx.x == 0) {
        int acc = 0;
        for (int i = 0; i < nblocks; i++) {
            int t = g_partial[i];
            g_partial[i] = acc;
            acc += t;
        }
    }
}

__global__ void k_scan3() {
    int i = blockIdx.x * blockDim.x + threadIdx.x;
    if (i < N_NODES) {
        int rp = g_rowptr[i] + g_partial[i >> 10];
        g_rowptr[i] = rp;
        g_cursor[i] = rp;
    }
    if (i == 0) g_rowptr[N_NODES] = N_EDGES;
}

__global__ void k_scatter(const int* __restrict__ ei_w) {
    int e = blockIdx.x * blockDim.x + threadIdx.x;
    if (e >= N_EDGES) return;
    int st = g_stride;
    int s = ei_w[(size_t)e * st];
    int d = ei_w[(size_t)N_EDGES * st + (size_t)e * st];
    if ((unsigned)s >= N_NODES || (unsigned)d >= N_NODES) return;
    int pos = atomicAdd(&g_cursor[d], 1);
    if ((unsigned)pos < N_EDGES) {
        g_col[pos] = s;
        g_w[pos] = g_dis[s] * g_dis[d];
    }
}

// ---------------- combined weight: Wc = W_in @ W0, bc = b_in @ W0 ----------------
__global__ void k_combine(const float* __restrict__ Win,
                          const float* __restrict__ bin,
                          const float* __restrict__ W0) {
    int c = threadIdx.x;  // 128 threads, one output column each
    float acc[IN_DIM];
    #pragma unroll
    for (int k = 0; k < IN_DIM; k++) acc[k] = 0.f;
    float bacc = 0.f;
    for (int j = 0; j < HID; j++) {
        float w = W0[j * HID + c];
        bacc += bin[j] * w;
        #pragma unroll
        for (int k = 0; k < IN_DIM; k++) acc[k] += Win[k * HID + j] * w;
    }
    #pragma unroll
    for (int k = 0; k < IN_DIM; k++) g_Wc[k * HID + c] = acc[k];
    g_bc[c] = bacc;
}

// -------- layer-0 fused transform: g_m = x @ Wc + bc  (K=16) --------
// Warp-per-node, W slice register-resident (16 float4 = 64 regs per lane).
#define F0_BLOCKS 1024
__global__ void __launch_bounds__(256) k_fused0(const float* __restrict__ x) {
    int tid = threadIdx.x;
    int lane = tid & 31;
    int warp_gid = (blockIdx.x * 256 + tid) >> 5;
    const int total_warps = F0_BLOCKS * 8;
    int c4 = lane * 4;

    float4 Wr[IN_DIM];
    #pragma unroll
    for (int k = 0; k < IN_DIM; k++)
        Wr[k] = *(const float4*)&g_Wc[k * HID + c4];
    float4 bs = *(const float4*)&g_bc[c4];

    for (int n = warp_gid; n < N_NODES; n += total_warps) {
        const float4* xr = (const float4*)(x + (size_t)n * IN_DIM);
        float4 xv0 = xr[0], xv1 = xr[1], xv2 = xr[2], xv3 = xr[3];
        float xk[IN_DIM] = {xv0.x, xv0.y, xv0.z, xv0.w,
                            xv1.x, xv1.y, xv1.z, xv1.w,
                            xv2.x, xv2.y, xv2.z, xv2.w,
                            xv3.x, xv3.y, xv3.z, xv3.w};
        float4 acc = bs;
        #pragma unroll
        for (int k = 0; k < IN_DIM; k++) {
            acc.x += xk[k] * Wr[k].x;
            acc.y += xk[k] * Wr[k].y;
            acc.z += xk[k] * Wr[k].z;
            acc.w += xk[k] * Wr[k].w;
        }
        *(float4*)&g_m[(size_t)n * HID + c4] = acc;
    }
}

// ---------------- GEMM: g_m = h(sel) @ W  (100000 x 128 x 128) ----------------
__global__ void __launch_bounds__(256) k_gemm(int hsel, const float* __restrict__ W) {
    extern __shared__ float Ws[];  // HID*HID floats = 64KB
    int tid = threadIdx.x;
    for (int i = tid; i < (HID * HID) / 4; i += 256)
        ((float4*)Ws)[i] = ((const float4*)W)[i];
    __syncthreads();

    const float* __restrict__ h = buf_sel(hsel);

    int row0 = blockIdx.x * 64 + (tid >> 5) * 8;
    int c4 = (tid & 31) * 4;

    const float* hp[8];
    #pragma unroll
    for (int r = 0; r < 8; r++) {
        int row = row0 + r;
        if (row >= N_NODES) row = N_NODES - 1;
        hp[r] = h + (size_t)row * HID;
    }

    float4 acc[8];
    #pragma unroll
    for (int r = 0; r < 8; r++) acc[r] = make_float4(0.f, 0.f, 0.f, 0.f);

    for (int k = 0; k < HID; k += 4) {
        float4 wv0 = *(const float4*)&Ws[(k + 0) * HID + c4];
        float4 wv1 = *(const float4*)&Ws[(k + 1) * HID + c4];
        float4 wv2 = *(const float4*)&Ws[(k + 2) * HID + c4];
        float4 wv3 = *(const float4*)&Ws[(k + 3) * HID + c4];
        #pragma unroll
        for (int r = 0; r < 8; r++) {
            float4 hv = *(const float4*)(hp[r] + k);
            acc[r].x += hv.x * wv0.x + hv.y * wv1.x + hv.z * wv2.x + hv.w * wv3.x;
            acc[r].y += hv.x * wv0.y + hv.y * wv1.y + hv.z * wv2.y + hv.w * wv3.y;
            acc[r].z += hv.x * wv0.z + hv.y * wv1.z + hv.z * wv2.z + hv.w * wv3.z;
            acc[r].w += hv.x * wv0.w + hv.y * wv1.w + hv.z * wv2.w + hv.w * wv3.w;
        }
    }
    #pragma unroll
    for (int r = 0; r < 8; r++) {
        int row = row0 + r;
        if (row < N_NODES)
            *(float4*)&g_m[(size_t)row * HID + c4] = acc[r];
    }
}

// -------- aggregation + bias + LayerNorm + ReLU + residual --------
__global__ void k_agg(const float* __restrict__ bconv,
                      const float* __restrict__ gamma,
                      const float* __restrict__ beta,
                      int prevsel, int outsel, float* out_ext) {
    int warp = (blockIdx.x * blockDim.x + threadIdx.x) >> 5;
    int lane = threadIdx.x & 31;
    if (warp >= N_NODES) return;
    int i = warp;

    float di = g_dis[i];
    float sc = di * di;
    float4 acc = *(const float4*)&g_m[(size_t)i * HID + lane * 4];
    acc.x *= sc; acc.y *= sc; acc.z *= sc; acc.w *= sc;

    int e0 = g_rowptr[i], e1 = g_rowptr[i + 1];
    int e = e0;
    for (; e + 2 <= e1; e += 2) {
        int s0 = g_col[e], s1 = g_col[e + 1];
        float w0 = g_w[e], w1 = g_w[e + 1];
        float4 m0 = *(const float4*)&g_m[(size_t)s0 * HID + lane * 4];
        float4 m1 = *(const float4*)&g_m[(size_t)s1 * HID + lane * 4];
        acc.x += m0.x * w0 + m1.x * w1;
        acc.y += m0.y * w0 + m1.y * w1;
        acc.z += m0.z * w0 + m1.z * w1;
        acc.w += m0.w * w0 + m1.w * w1;
    }
    if (e < e1) {
        int s0 = g_col[e];
        float w0 = g_w[e];
        float4 m0 = *(const float4*)&g_m[(size_t)s0 * HID + lane * 4];
        acc.x += m0.x * w0;
        acc.y += m0.y * w0;
        acc.z += m0.z * w0;
        acc.w += m0.w * w0;
    }

    float4 bv = *(const float4*)&bconv[lane * 4];
    acc.x += bv.x; acc.y += bv.y; acc.z += bv.z; acc.w += bv.w;

    // LayerNorm over 128 values held as 4/lane within the warp
    float sum = acc.x + acc.y + acc.z + acc.w;
    float sumsq = acc.x * acc.x + acc.y * acc.y + acc.z * acc.z + acc.w * acc.w;
    #pragma unroll
    for (int o = 16; o >= 1; o >>= 1) {
        sum += __shfl_xor_sync(0xFFFFFFFFu, sum, o);
        sumsq += __shfl_xor_sync(0xFFFFFFFFu, sumsq, o);
    }
    float mu = sum * (1.0f / HID);
    float var = sumsq * (1.0f / HID) - mu * mu;
    float inv = rsqrtf(var + LN_EPS);

    float4 gv = *(const float4*)&gamma[lane * 4];
    float4 btv = *(const float4*)&beta[lane * 4];
    float4 o4;
    o4.x = fmaxf((acc.x - mu) * inv * gv.x + btv.x, 0.f);
    o4.y = fmaxf((acc.y - mu) * inv * gv.y + btv.y, 0.f);
    o4.z = fmaxf((acc.z - mu) * inv * gv.z + btv.z, 0.f);
    o4.w = fmaxf((acc.w - mu) * inv * gv.w + btv.w, 0.f);

    if (prevsel >= 0) {
        const float* hprev = buf_sel(prevsel);
        float4 hp = *(const float4*)&hprev[(size_t)i * HID + lane * 4];
        o4.x += hp.x; o4.y += hp.y; o4.z += hp.z; o4.w += hp.w;
    }

    float* out = (outsel == 2) ? out_ext : buf_sel(outsel);
    *(float4*)&out[(size_t)i * HID + lane * 4] = o4;
}

// ---------------- launch ----------------
extern "C" void kernel_launch(void* const* d_in, const int* in_sizes, int n_in,
                              void* d_out, int out_size) {
    const float* x     = (const float*)d_in[0];
    const int*   ei_w  = (const int*)d_in[1];   // edge_index words (int32 view)
    const float* Win   = (const float*)d_in[2];
    const float* bin   = (const float*)d_in[3];
    const float* Wconv = (const float*)d_in[4];  // [3,128,128]
    const float* bconv = (const float*)d_in[5];  // [3,128]
    const float* gamma = (const float*)d_in[6];  // [3,128]
    const float* beta  = (const float*)d_in[7];  // [3,128]
    float* out = (float*)d_out;

    cudaFuncSetAttribute(k_gemm, cudaFuncAttributeMaxDynamicSharedMemorySize,
                         HID * HID * sizeof(float));

    const int NODE_BLOCKS = (N_NODES + 255) / 256;
    const int EDGE_BLOCKS = (N_EDGES + 255) / 256;
    const int SCAN_BLOCKS = (N_NODES + 1023) / 1024;

    // Profiled launch slot is index 3 -> k_count this round.
    k_combine<<<1, HID>>>(Win, bin, Wconv + 0 * HID * HID);   // 0
    k_detect<<<1, 32>>>(ei_w);                                 // 1
    k_zero_cnt<<<NODE_BLOCKS, 256>>>();                        // 2
    k_count<<<EDGE_BLOCKS, 256>>>(ei_w);                       // 3 <- profiled
    k_deg<<<NODE_BLOCKS, 256>>>();                             // 4
    k_scan1<<<SCAN_BLOCKS, 1024>>>();                          // 5
    k_scan2<<<1, 32>>>(SCAN_BLOCKS);                           // 6
    k_scan3<<<NODE_BLOCKS, 256>>>();                           // 7
    k_scatter<<<EDGE_BLOCKS, 256>>>(ei_w);                     // 8
    k_fused0<<<F0_BLOCKS, 256>>>(x);                           // 9

    const int GEMM_BLOCKS = (N_NODES + 63) / 64;
    const int AGG_BLOCKS = (N_NODES * 32 + 255) / 256;
    const size_t WSM = HID * HID * sizeof(float);

    // layer 0 agg: -> h1 (no residual)
    k_agg<<<AGG_BLOCKS, 256>>>(bconv + 0 * HID, gamma + 0 * HID, beta + 0 * HID,
                               -1, 1, nullptr);
    // layer 1: h1 -> h0 (+ residual h1)
    k_gemm<<<GEMM_BLOCKS, 256, WSM>>>(1, Wconv + 1 * HID * HID);
    k_agg<<<AGG_BLOCKS, 256>>>(bconv + 1 * HID, gamma + 1 * HID, beta + 1 * HID,
                               1, 0, nullptr);
    // layer 2: h0 -> out (+ residual h0)
    k_gemm<<<GEMM_BLOCKS, 256, WSM>>>(0, Wconv + 2 * HID * HID);
    k_agg<<<AGG_BLOCKS, 256>>>(bconv + 2 * HID, gamma + 2 * HID, beta + 2 * HID,
                               0, 2, out);
}

// round 9
// speedup vs baseline: 1.4402x; 1.2968x over previous
#include <cuda_runtime.h>
#include <cuda_bf16.h>
#include <cstdint>

#define N_NODES 100000
#define N_EDGES 1600000
#define IN_DIM  16
#define HID     128
#define LN_EPS  1e-5f

#define TILE_M  128
#define GEMM_TILES ((N_NODES + TILE_M - 1) / TILE_M)

// SMEM layout for mma GEMM: 4 bf16 tiles of 128 x 128, rows padded to 272B
#define PADB    272
#define TILE_BYTES (128 * PADB)            // 34816
#define OFF_AHI 0
#define OFF_ALO TILE_BYTES
#define OFF_BHI (2 * TILE_BYTES)
#define OFF_BLO (3 * TILE_BYTES)
#define SM_GEMM (4 * TILE_BYTES)           // 139264

// ---------------- scratch (no allocation allowed) ----------------
__device__ float g_dis[N_NODES];
__device__ int   g_cnt[N_NODES];
__device__ int   g_rowptr[N_NODES + 1];
__device__ int   g_cursor[N_NODES];
__device__ int   g_partial[128];
__device__ int   g_col[N_EDGES];
__device__ float g_w[N_EDGES];
__device__ float g_m[(size_t)N_NODES * HID];
__device__ float g_h0[(size_t)N_NODES * HID];
__device__ float g_h1[(size_t)N_NODES * HID];
__device__ float g_Wc[IN_DIM * HID];
__device__ float g_bc[HID];
__device__ int   g_stride;

__device__ __forceinline__ float* buf_sel(int s) {
    return (s == 0) ? g_h0 : g_h1;
}

// ---------------- helpers ----------------
__device__ __forceinline__ uint32_t smem_u32(const void* p) {
    uint32_t a;
    asm("{ .reg .u64 t; cvta.to.shared.u64 t, %1; cvt.u32.u64 %0, t; }" : "=r"(a) : "l"(p));
    return a;
}
__device__ __forceinline__ uint32_t bfpack(float a, float b) {
    __nv_bfloat162 t = __floats2bfloat162_rn(a, b);
    return *reinterpret_cast<uint32_t*>(&t);
}
__device__ __forceinline__ void bfsplit(float v, float& hi, float& lo) {
    __nv_bfloat16 h = __float2bfloat16(v);
    hi = __bfloat162float(h);
    lo = v - hi;
}
__device__ __forceinline__ void ldsm_x4(uint32_t& r0, uint32_t& r1, uint32_t& r2,
                                        uint32_t& r3, uint32_t addr) {
    asm volatile("ldmatrix.sync.aligned.m8n8.x4.shared.b16 {%0,%1,%2,%3}, [%4];"
                 : "=r"(r0), "=r"(r1), "=r"(r2), "=r"(r3) : "r"(addr));
}
__device__ __forceinline__ void ldsm_x4t(uint32_t& r0, uint32_t& r1, uint32_t& r2,
                                         uint32_t& r3, uint32_t addr) {
    asm volatile("ldmatrix.sync.aligned.m8n8.x4.trans.shared.b16 {%0,%1,%2,%3}, [%4];"
                 : "=r"(r0), "=r"(r1), "=r"(r2), "=r"(r3) : "r"(addr));
}
__device__ __forceinline__ void mma_bf16(float* d, const uint32_t* a,
                                         uint32_t b0, uint32_t b1) {
    asm volatile(
        "mma.sync.aligned.m16n8k16.row.col.f32.bf16.bf16.f32 "
        "{%0,%1,%2,%3}, {%4,%5,%6,%7}, {%8,%9}, {%0,%1,%2,%3};"
        : "+f"(d[0]), "+f"(d[1]), "+f"(d[2]), "+f"(d[3])
        : "r"(a[0]), "r"(a[1]), "r"(a[2]), "r"(a[3]), "r"(b0), "r"(b1));
}

// ---------------- dtype detection ----------------
__global__ void k_detect(const int* __restrict__ ei_w) {
    if (threadIdx.x == 0) {
        bool all_zero = true;
        for (int i = 0; i < 32; i++)
            if (ei_w[2 * i + 1] != 0) { all_zero = false; break; }
        g_stride = all_zero ? 2 : 1;
    }
}

// ---------------- graph preprocessing ----------------
__global__ void k_zero_cnt() {
    int i = blockIdx.x * blockDim.x + threadIdx.x;
    if (i < N_NODES) g_cnt[i] = 0;
}

__global__ void k_count(const int* __restrict__ ei_w) {
    int e = blockIdx.x * blockDim.x + threadIdx.x;
    if (e >= N_EDGES) return;
    int st = g_stride;
    int d = ei_w[(size_t)N_EDGES * st + (size_t)e * st];
    if ((unsigned)d < N_NODES) atomicAdd(&g_cnt[d], 1);
}

__global__ void k_deg() {
    int i = blockIdx.x * blockDim.x + threadIdx.x;
    if (i < N_NODES) g_dis[i] = rsqrtf((float)(g_cnt[i] + 1));
}

__global__ void k_scan1() {
    __shared__ int warp_sums[32];
    int tid = threadIdx.x;
    int gid = blockIdx.x * 1024 + tid;
    int v = (gid < N_NODES) ? g_cnt[gid] : 0;
    int lane = tid & 31, wid = tid >> 5;
    int x = v;
    #pragma unroll
    for (int o = 1; o < 32; o <<= 1) {
        int y = __shfl_up_sync(0xFFFFFFFFu, x, o);
        if (lane >= o) x += y;
    }
    if (lane == 31) warp_sums[wid] = x;
    __syncthreads();
    if (wid == 0) {
        int s = warp_sums[lane];
        #pragma unroll
        for (int o = 1; o < 32; o <<= 1) {
            int y = __shfl_up_sync(0xFFFFFFFFu, s, o);
            if (lane >= o) s += y;
        }
        warp_sums[lane] = s;
    }
    __syncthreads();
    int base = (wid > 0) ? warp_sums[wid - 1] : 0;
    if (gid < N_NODES) g_rowptr[gid] = base + x - v;
    if (tid == 1023) g_partial[blockIdx.x] = base + x;
}

__global__ void k_scan2(int nblocks) {
    if (threadIdx.x == 0 && blockIdx.x == 0) {
        int acc = 0;
        for (int i = 0; i < nblocks; i++) {
            int t = g_partial[i];
            g_partial[i] = acc;
            acc += t;
        }
    }
}

__global__ void k_scan3() {
    int i = blockIdx.x * blockDim.x + threadIdx.x;
    if (i < N_NODES) {
        int rp = g_rowptr[i] + g_partial[i >> 10];
        g_rowptr[i] = rp;
        g_cursor[i] = rp;
    }
    if (i == 0) g_rowptr[N_NODES] = N_EDGES;
}

__global__ void k_scatter(const int* __restrict__ ei_w) {
    int e = blockIdx.x * blockDim.x + threadIdx.x;
    if (e >= N_EDGES) return;
    int st = g_stride;
    int s = ei_w[(size_t)e * st];
    int d = ei_w[(size_t)N_EDGES * st + (size_t)e * st];
    if ((unsigned)s >= N_NODES || (unsigned)d >= N_NODES) return;
    int pos = atomicAdd(&g_cursor[d], 1);
    if ((unsigned)pos < N_EDGES) {
        g_col[pos] = s;
        g_w[pos] = g_dis[s] * g_dis[d];
    }
}

// ---------------- combined weight: Wc = W_in @ W0, bc = b_in @ W0 ----------------
__global__ void k_combine(const float* __restrict__ Win,
                          const float* __restrict__ bin,
                          const float* __restrict__ W0) {
    int c = threadIdx.x;
    float acc[IN_DIM];
    #pragma unroll
    for (int k = 0; k < IN_DIM; k++) acc[k] = 0.f;
    float bacc = 0.f;
    for (int j = 0; j < HID; j++) {
        float w = W0[j * HID + c];
        bacc += bin[j] * w;
        #pragma unroll
        for (int k = 0; k < IN_DIM; k++) acc[k] += Win[k * HID + j] * w;
    }
    #pragma unroll
    for (int k = 0; k < IN_DIM; k++) g_Wc[k * HID + c] = acc[k];
    g_bc[c] = bacc;
}

// -------- layer-0 fused transform: g_m = x @ Wc + bc  (K=16) --------
#define F0_BLOCKS 1024
__global__ void __launch_bounds__(256) k_fused0(const float* __restrict__ x) {
    int tid = threadIdx.x;
    int lane = tid & 31;
    int warp_gid = (blockIdx.x * 256 + tid) >> 5;
    const int total_warps = F0_BLOCKS * 8;
    int c4 = lane * 4;

    float4 Wr[IN_DIM];
    #pragma unroll
    for (int k = 0; k < IN_DIM; k++)
        Wr[k] = *(const float4*)&g_Wc[k * HID + c4];
    float4 bs = *(const float4*)&g_bc[c4];

    for (int n = warp_gid; n < N_NODES; n += total_warps) {
        const float4* xr = (const float4*)(x + (size_t)n * IN_DIM);
        float4 xv0 = xr[0], xv1 = xr[1], xv2 = xr[2], xv3 = xr[3];
        float xk[IN_DIM] = {xv0.x, xv0.y, xv0.z, xv0.w,
                            xv1.x, xv1.y, xv1.z, xv1.w,
                            xv2.x, xv2.y, xv2.z, xv2.w,
                            xv3.x, xv3.y, xv3.z, xv3.w};
        float4 acc = bs;
        #pragma unroll
        for (int k = 0; k < IN_DIM; k++) {
            acc.x += xk[k] * Wr[k].x;
            acc.y += xk[k] * Wr[k].y;
            acc.z += xk[k] * Wr[k].z;
            acc.w += xk[k] * Wr[k].w;
        }
        *(float4*)&g_m[(size_t)n * HID + c4] = acc;
    }
}

// ---------------- mma.sync bf16 3-term GEMM: g_m = h(sel) @ W ----------------
__global__ void __launch_bounds__(256, 1) k_gemm_mma(int hsel, const float* __restrict__ W) {
    extern __shared__ char sm[];
    int tid = threadIdx.x;
    const float* __restrict__ h = buf_sel(hsel);
    int row0 = blockIdx.x * TILE_M;

    // ---- fill A (h rows) hi/lo ----
    #pragma unroll
    for (int j = 0; j < 16; j++) {
        int f = tid + 256 * j;           // float4 index in [0, 4096)
        int r = f >> 5, kg = f & 31;
        int row = row0 + r;
        if (row >= N_NODES) row = N_NODES - 1;
        float4 v = *(const float4*)&h[(size_t)row * HID + kg * 4];
        float h0, l0, h1, l1, h2, l2, h3, l3;
        bfsplit(v.x, h0, l0); bfsplit(v.y, h1, l1);
        bfsplit(v.z, h2, l2); bfsplit(v.w, h3, l3);
        uint2 hp, lp;
        hp.x = bfpack(h0, h1); hp.y = bfpack(h2, h3);
        lp.x = bfpack(l0, l1); lp.y = bfpack(l2, l3);
        *(uint2*)(sm + OFF_AHI + r * PADB + kg * 8) = hp;
        *(uint2*)(sm + OFF_ALO + r * PADB + kg * 8) = lp;
    }
    // ---- fill B (W, k-major rows) hi/lo ----
    #pragma unroll
    for (int j = 0; j < 16; j++) {
        int f = tid + 256 * j;
        int k = f >> 5, ng = f & 31;
        float4 v = *(const float4*)&W[(size_t)k * HID + ng * 4];
        float h0, l0, h1, l1, h2, l2, h3, l3;
        bfsplit(v.x, h0, l0); bfsplit(v.y, h1, l1);
        bfsplit(v.z, h2, l2); bfsplit(v.w, h3, l3);
        uint2 hp, lp;
        hp.x = bfpack(h0, h1); hp.y = bfpack(h2, h3);
        lp.x = bfpack(l0, l1); lp.y = bfpack(l2, l3);
        *(uint2*)(sm + OFF_BHI + k * PADB + ng * 8) = hp;
        *(uint2*)(sm + OFF_BLO + k * PADB + ng * 8) = lp;
    }
    __syncthreads();

    int lane = tid & 31, w = tid >> 5;
    uint32_t sbase = smem_u32(sm);

    float acc[16][4];
    #pragma unroll
    for (int t = 0; t < 16; t++)
        #pragma unroll
        for (int i = 0; i < 4; i++) acc[t][i] = 0.f;

    // A tile base for this warp: rows w*16..+16; lane -> row (lane&15), k-half (lane>>4)
    uint32_t a_row_addr = sbase + OFF_AHI + (w * 16 + (lane & 15)) * PADB + (lane >> 4) * 16;

    #pragma unroll
    for (int ks = 0; ks < 8; ks++) {
        uint32_t ah[4], al[4];
        uint32_t aaddr = a_row_addr + ks * 32;
        ldsm_x4(ah[0], ah[1], ah[2], ah[3], aaddr);
        ldsm_x4(al[0], al[1], al[2], al[3], aaddr + TILE_BYTES);

        // B: lane -> k-row (lane&15) of this k-step, n-half (lane>>4)*8
        uint32_t b_base = sbase + OFF_BHI + (ks * 16 + (lane & 15)) * PADB + (lane >> 4) * 16;
        #pragma unroll
        for (int ntp = 0; ntp < 8; ntp++) {
            uint32_t bh0, bh1, bh2, bh3, bl0, bl1, bl2, bl3;
            ldsm_x4t(bh0, bh1, bh2, bh3, b_base + ntp * 32);
            ldsm_x4t(bl0, bl1, bl2, bl3, b_base + TILE_BYTES + ntp * 32);
            mma_bf16(acc[2 * ntp + 0], ah, bh0, bh1);
            mma_bf16(acc[2 * ntp + 1], ah, bh2, bh3);
            mma_bf16(acc[2 * ntp + 0], ah, bl0, bl1);
            mma_bf16(acc[2 * ntp + 1], ah, bl2, bl3);
            mma_bf16(acc[2 * ntp + 0], al, bh0, bh1);
            mma_bf16(acc[2 * ntp + 1], al, bh2, bh3);
        }
    }

    // epilogue: d0,d1 -> row lane/4, cols (lane&3)*2 + {0,1}; d2,d3 -> row+8
    int r0 = row0 + w * 16 + (lane >> 2);
    int r1 = r0 + 8;
    int cb = (lane & 3) * 2;
    #pragma unroll
    for (int nt = 0; nt < 16; nt++) {
        if (r0 < N_NODES)
            *(float2*)&g_m[(size_t)r0 * HID + nt * 8 + cb] =
                make_float2(acc[nt][0], acc[nt][1]);
        if (r1 < N_NODES)
            *(float2*)&g_m[(size_t)r1 * HID + nt * 8 + cb] =
                make_float2(acc[nt][2], acc[nt][3]);
    }
}

// -------- aggregation + bias + LayerNorm + ReLU + residual --------
__global__ void k_agg(const float* __restrict__ bconv,
                      const float* __restrict__ gamma,
                      const float* __restrict__ beta,
                      int prevsel, int outsel, float* out_ext) {
    int warp = (blockIdx.x * blockDim.x + threadIdx.x) >> 5;
    int lane = threadIdx.x & 31;
    if (warp >= N_NODES) return;
    int i = warp;

    float di = g_dis[i];
    float sc = di * di;
    float4 acc = *(const float4*)&g_m[(size_t)i * HID + lane * 4];
    acc.x *= sc; acc.y *= sc; acc.z *= sc; acc.w *= sc;

    int e0 = g_rowptr[i], e1 = g_rowptr[i + 1];
    int e = e0;
    for (; e + 2 <= e1; e += 2) {
        int s0 = g_col[e], s1 = g_col[e + 1];
        float w0 = g_w[e], w1 = g_w[e + 1];
        float4 m0 = *(const float4*)&g_m[(size_t)s0 * HID + lane * 4];
        float4 m1 = *(const float4*)&g_m[(size_t)s1 * HID + lane * 4];
        acc.x += m0.x * w0 + m1.x * w1;
        acc.y += m0.y * w0 + m1.y * w1;
        acc.z += m0.z * w0 + m1.z * w1;
        acc.w += m0.w * w0 + m1.w * w1;
    }
    if (e < e1) {
        int s0 = g_col[e];
        float w0 = g_w[e];
        float4 m0 = *(const float4*)&g_m[(size_t)s0 * HID + lane * 4];
        acc.x += m0.x * w0;
        acc.y += m0.y * w0;
        acc.z += m0.z * w0;
        acc.w += m0.w * w0;
    }

    float4 bv = *(const float4*)&bconv[lane * 4];
    acc.x += bv.x; acc.y += bv.y; acc.z += bv.z; acc.w += bv.w;

    float sum = acc.x + acc.y + acc.z + acc.w;
    float sumsq = acc.x * acc.x + acc.y * acc.y + acc.z * acc.z + acc.w * acc.w;
    #pragma unroll
    for (int o = 16; o >= 1; o >>= 1) {
        sum += __shfl_xor_sync(0xFFFFFFFFu, sum, o);
        sumsq += __shfl_xor_sync(0xFFFFFFFFu, sumsq, o);
    }
    float mu = sum * (1.0f / HID);
    float var = sumsq * (1.0f / HID) - mu * mu;
    float inv = rsqrtf(var + LN_EPS);

    float4 gv = *(const float4*)&gamma[lane * 4];
    float4 btv = *(const float4*)&beta[lane * 4];
    float4 o4;
    o4.x = fmaxf((acc.x - mu) * inv * gv.x + btv.x, 0.f);
    o4.y = fmaxf((acc.y - mu) * inv * gv.y + btv.y, 0.f);
    o4.z = fmaxf((acc.z - mu) * inv * gv.z + btv.z, 0.f);
    o4.w = fmaxf((acc.w - mu) * inv * gv.w + btv.w, 0.f);

    if (prevsel >= 0) {
        const float* hprev = buf_sel(prevsel);
        float4 hp = *(const float4*)&hprev[(size_t)i * HID + lane * 4];
        o4.x += hp.x; o4.y += hp.y; o4.z += hp.z; o4.w += hp.w;
    }

    float* out = (outsel == 2) ? out_ext : buf_sel(outsel);
    *(float4*)&out[(size_t)i * HID + lane * 4] = o4;
}

// ---------------- launch ----------------
extern "C" void kernel_launch(void* const* d_in, const int* in_sizes, int n_in,
                              void* d_out, int out_size) {
    const float* x     = (const float*)d_in[0];
    const int*   ei_w  = (const int*)d_in[1];
    const float* Win   = (const float*)d_in[2];
    const float* bin   = (const float*)d_in[3];
    const float* Wconv = (const float*)d_in[4];
    const float* bconv = (const float*)d_in[5];
    const float* gamma = (const float*)d_in[6];
    const float* beta  = (const float*)d_in[7];
    float* out = (float*)d_out;

    cudaFuncSetAttribute(k_gemm_mma, cudaFuncAttributeMaxDynamicSharedMemorySize, SM_GEMM);

    const int NODE_BLOCKS = (N_NODES + 255) / 256;
    const int EDGE_BLOCKS = (N_EDGES + 255) / 256;
    const int SCAN_BLOCKS = (N_NODES + 1023) / 1024;

    k_combine<<<1, HID>>>(Win, bin, Wconv + 0 * HID * HID);   // 0
    k_detect<<<1, 32>>>(ei_w);                                 // 1
    k_zero_cnt<<<NODE_BLOCKS, 256>>>();                        // 2
    k_count<<<EDGE_BLOCKS, 256>>>(ei_w);                       // 3 <- profiled slot
    k_deg<<<NODE_BLOCKS, 256>>>();                             // 4
    k_scan1<<<SCAN_BLOCKS, 1024>>>();                          // 5
    k_scan2<<<1, 32>>>(SCAN_BLOCKS);                           // 6
    k_scan3<<<NODE_BLOCKS, 256>>>();                           // 7
    k_scatter<<<EDGE_BLOCKS, 256>>>(ei_w);                     // 8
    k_fused0<<<F0_BLOCKS, 256>>>(x);                           // 9

    const int AGG_BLOCKS = (N_NODES * 32 + 255) / 256;

    // layer 0 agg: -> h1 (no residual)
    k_agg<<<AGG_BLOCKS, 256>>>(bconv + 0 * HID, gamma + 0 * HID, beta + 0 * HID,
                               -1, 1, nullptr);
    // layer 1: h1 -> h0 (+ residual h1)
    k_gemm_mma<<<GEMM_TILES, 256, SM_GEMM>>>(1, Wconv + 1 * HID * HID);
    k_agg<<<AGG_BLOCKS, 256>>>(bconv + 1 * HID, gamma + 1 * HID, beta + 1 * HID,
                               1, 0, nullptr);
    // layer 2: h0 -> out (+ residual h0)
    k_gemm_mma<<<GEMM_TILES, 256, SM_GEMM>>>(0, Wconv + 2 * HID * HID);
    k_agg<<<AGG_BLOCKS, 256>>>(bconv + 2 * HID, gamma + 2 * HID, beta + 2 * HID,
                               0, 2, out);
}

// round 10
// speedup vs baseline: 1.4547x; 1.0100x over previous
#include <cuda_runtime.h>
#include <cuda_bf16.h>
#include <cstdint>

#define N_NODES 100000
#define N_EDGES 1600000
#define IN_DIM  16
#define HID     128
#define LN_EPS  1e-5f

#define TILE_M  128
#define GEMM_TILES ((N_NODES + TILE_M - 1) / TILE_M)

// SMEM layout for mma GEMM: 4 bf16 tiles of 128 x 128, rows padded to 272B
#define PADB    272
#define TILE_BYTES (128 * PADB)            // 34816
#define OFF_AHI 0
#define OFF_ALO TILE_BYTES
#define OFF_BHI (2 * TILE_BYTES)
#define OFF_BLO (3 * TILE_BYTES)
#define SM_GEMM (4 * TILE_BYTES)           // 139264

// k_mma0 (K=16) layout: A rows padded to 48B, B rows padded to 272B
#define PADA0   48
#define A0_BYTES (128 * PADA0)             // 6144
#define B0_BYTES (16 * PADB)               // 4352

// ---------------- scratch (no allocation allowed) ----------------
__device__ float g_dis[N_NODES];
__device__ int   g_cnt[N_NODES];
__device__ int   g_rowptr[N_NODES + 1];
__device__ int   g_cursor[N_NODES];
__device__ int   g_partial[128];
__device__ int   g_col[N_EDGES];
__device__ float g_w[N_EDGES];
__device__ float g_m[(size_t)N_NODES * HID];
__device__ float g_h0[(size_t)N_NODES * HID];
__device__ float g_h1[(size_t)N_NODES * HID];
__device__ float g_Wc[IN_DIM * HID];
__device__ float g_bc[HID];
__device__ int   g_stride;

__device__ __forceinline__ float* buf_sel(int s) {
    return (s == 0) ? g_h0 : g_h1;
}

// ---------------- helpers ----------------
__device__ __forceinline__ uint32_t smem_u32(const void* p) {
    uint32_t a;
    asm("{ .reg .u64 t; cvta.to.shared.u64 t, %1; cvt.u32.u64 %0, t; }" : "=r"(a) : "l"(p));
    return a;
}
__device__ __forceinline__ uint32_t bfpack(float a, float b) {
    __nv_bfloat162 t = __floats2bfloat162_rn(a, b);
    return *reinterpret_cast<uint32_t*>(&t);
}
__device__ __forceinline__ void bfsplit(float v, float& hi, float& lo) {
    __nv_bfloat16 h = __float2bfloat16(v);
    hi = __bfloat162float(h);
    lo = v - hi;
}
__device__ __forceinline__ void ldsm_x4(uint32_t& r0, uint32_t& r1, uint32_t& r2,
                                        uint32_t& r3, uint32_t addr) {
    asm volatile("ldmatrix.sync.aligned.m8n8.x4.shared.b16 {%0,%1,%2,%3}, [%4];"
                 : "=r"(r0), "=r"(r1), "=r"(r2), "=r"(r3) : "r"(addr));
}
__device__ __forceinline__ void ldsm_x4t(uint32_t& r0, uint32_t& r1, uint32_t& r2,
                                         uint32_t& r3, uint32_t addr) {
    asm volatile("ldmatrix.sync.aligned.m8n8.x4.trans.shared.b16 {%0,%1,%2,%3}, [%4];"
                 : "=r"(r0), "=r"(r1), "=r"(r2), "=r"(r3) : "r"(addr));
}
__device__ __forceinline__ void mma_bf16(float* d, const uint32_t* a,
                                         uint32_t b0, uint32_t b1) {
    asm volatile(
        "mma.sync.aligned.m16n8k16.row.col.f32.bf16.bf16.f32 "
        "{%0,%1,%2,%3}, {%4,%5,%6,%7}, {%8,%9}, {%0,%1,%2,%3};"
        : "+f"(d[0]), "+f"(d[1]), "+f"(d[2]), "+f"(d[3])
        : "r"(a[0]), "r"(a[1]), "r"(a[2]), "r"(a[3]), "r"(b0), "r"(b1));
}

// ---------------- dtype detection ----------------
__global__ void k_detect(const int* __restrict__ ei_w) {
    if (threadIdx.x == 0) {
        bool all_zero = true;
        for (int i = 0; i < 32; i++)
            if (ei_w[2 * i + 1] != 0) { all_zero = false; break; }
        g_stride = all_zero ? 2 : 1;
    }
}

// ---------------- graph preprocessing ----------------
__global__ void k_zero_cnt() {
    int i = blockIdx.x * blockDim.x + threadIdx.x;
    if (i < N_NODES) g_cnt[i] = 0;
}

__global__ void k_count(const int* __restrict__ ei_w) {
    int e = blockIdx.x * blockDim.x + threadIdx.x;
    if (e >= N_EDGES) return;
    int st = g_stride;
    int d = ei_w[(size_t)N_EDGES * st + (size_t)e * st];
    if ((unsigned)d < N_NODES) atomicAdd(&g_cnt[d], 1);
}

__global__ void k_scan1() {
    __shared__ int warp_sums[32];
    int tid = threadIdx.x;
    int gid = blockIdx.x * 1024 + tid;
    int v = (gid < N_NODES) ? g_cnt[gid] : 0;
    int lane = tid & 31, wid = tid >> 5;
    int x = v;
    #pragma unroll
    for (int o = 1; o < 32; o <<= 1) {
        int y = __shfl_up_sync(0xFFFFFFFFu, x, o);
        if (lane >= o) x += y;
    }
    if (lane == 31) warp_sums[wid] = x;
    __syncthreads();
    if (wid == 0) {
        int s = warp_sums[lane];
        #pragma unroll
        for (int o = 1; o < 32; o <<= 1) {
            int y = __shfl_up_sync(0xFFFFFFFFu, s, o);
            if (lane >= o) s += y;
        }
        warp_sums[lane] = s;
    }
    __syncthreads();
    int base = (wid > 0) ? warp_sums[wid - 1] : 0;
    if (gid < N_NODES) g_rowptr[gid] = base + x - v;
    if (tid == 1023) g_partial[blockIdx.x] = base + x;
}

__global__ void k_scan2(int nblocks) {
    if (threadIdx.x == 0 && blockIdx.x == 0) {
        int acc = 0;
        for (int i = 0; i < nblocks; i++) {
            int t = g_partial[i];
            g_partial[i] = acc;
            acc += t;
        }
    }
}

// scan3 + deg fused (g_cnt still valid here)
__global__ void k_scan3() {
    int i = blockIdx.x * blockDim.x + threadIdx.x;
    if (i < N_NODES) {
        int rp = g_rowptr[i] + g_partial[i >> 10];
        g_rowptr[i] = rp;
        g_cursor[i] = rp;
        g_dis[i] = rsqrtf((float)(g_cnt[i] + 1));  // +1 self loop
    }
    if (i == 0) g_rowptr[N_NODES] = N_EDGES;
}

__global__ void k_scatter(const int* __restrict__ ei_w) {
    int e = blockIdx.x * blockDim.x + threadIdx.x;
    if (e >= N_EDGES) return;
    int st = g_stride;
    int s = ei_w[(size_t)e * st];
    int d = ei_w[(size_t)N_EDGES * st + (size_t)e * st];
    if ((unsigned)s >= N_NODES || (unsigned)d >= N_NODES) return;
    int pos = atomicAdd(&g_cursor[d], 1);
    if ((unsigned)pos < N_EDGES) {
        g_col[pos] = s;
        g_w[pos] = g_dis[s] * g_dis[d];
    }
}

// ---------------- combined weight: Wc = W_in @ W0, bc = b_in @ W0 ----------------
__global__ void k_combine(const float* __restrict__ Win,
                          const float* __restrict__ bin,
                          const float* __restrict__ W0) {
    int c = threadIdx.x;
    float acc[IN_DIM];
    #pragma unroll
    for (int k = 0; k < IN_DIM; k++) acc[k] = 0.f;
    float bacc = 0.f;
    for (int j = 0; j < HID; j++) {
        float w = W0[j * HID + c];
        bacc += bin[j] * w;
        #pragma unroll
        for (int k = 0; k < IN_DIM; k++) acc[k] += Win[k * HID + j] * w;
    }
    #pragma unroll
    for (int k = 0; k < IN_DIM; k++) g_Wc[k * HID + c] = acc[k];
    g_bc[c] = bacc;
}

// -------- layer-0 fused transform via tensor cores: g_m = x @ Wc + bc (K=16) --------
__global__ void __launch_bounds__(256, 1) k_mma0(const float* __restrict__ x) {
    __shared__ char sm[2 * A0_BYTES + 2 * B0_BYTES];
    const int A_HI = 0, A_LO = A0_BYTES;
    const int B_HI = 2 * A0_BYTES, B_LO = 2 * A0_BYTES + B0_BYTES;
    int tid = threadIdx.x;
    int row0 = blockIdx.x * TILE_M;

    // ---- fill A (x rows, 128 x 16) hi/lo: 512 float4, 2 per thread ----
    #pragma unroll
    for (int j = 0; j < 2; j++) {
        int f = tid + 256 * j;           // [0, 512)
        int r = f >> 2, g = f & 3;       // row, float4-group
        int row = row0 + r;
        if (row >= N_NODES) row = N_NODES - 1;
        float4 v = *(const float4*)&x[(size_t)row * IN_DIM + g * 4];
        float h0, l0, h1, l1, h2, l2, h3, l3;
        bfsplit(v.x, h0, l0); bfsplit(v.y, h1, l1);
        bfsplit(v.z, h2, l2); bfsplit(v.w, h3, l3);
        uint2 hp, lp;
        hp.x = bfpack(h0, h1); hp.y = bfpack(h2, h3);
        lp.x = bfpack(l0, l1); lp.y = bfpack(l2, l3);
        *(uint2*)(sm + A_HI + r * PADA0 + g * 8) = hp;
        *(uint2*)(sm + A_LO + r * PADA0 + g * 8) = lp;
    }
    // ---- fill B (Wc, 16 x 128) hi/lo: 512 float4, 2 per thread ----
    #pragma unroll
    for (int j = 0; j < 2; j++) {
        int f = tid + 256 * j;
        int k = f >> 5, ng = f & 31;
        float4 v = *(const float4*)&g_Wc[k * HID + ng * 4];
        float h0, l0, h1, l1, h2, l2, h3, l3;
        bfsplit(v.x, h0, l0); bfsplit(v.y, h1, l1);
        bfsplit(v.z, h2, l2); bfsplit(v.w, h3, l3);
        uint2 hp, lp;
        hp.x = bfpack(h0, h1); hp.y = bfpack(h2, h3);
        lp.x = bfpack(l0, l1); lp.y = bfpack(l2, l3);
        *(uint2*)(sm + B_HI + k * PADB + ng * 8) = hp;
        *(uint2*)(sm + B_LO + k * PADB + ng * 8) = lp;
    }
    __syncthreads();

    int lane = tid & 31, w = tid >> 5;
    uint32_t sbase = smem_u32(sm);

    float acc[16][4];
    #pragma unroll
    for (int t = 0; t < 16; t++)
        #pragma unroll
        for (int i = 0; i < 4; i++) acc[t][i] = 0.f;

    uint32_t aaddr = sbase + A_HI + (w * 16 + (lane & 15)) * PADA0 + (lane >> 4) * 16;
    uint32_t ah[4], al[4];
    ldsm_x4(ah[0], ah[1], ah[2], ah[3], aaddr);
    ldsm_x4(al[0], al[1], al[2], al[3], aaddr + A0_BYTES);

    uint32_t b_base = sbase + B_HI + (lane & 15) * PADB + (lane >> 4) * 16;
    #pragma unroll
    for (int ntp = 0; ntp < 8; ntp++) {
        uint32_t bh0, bh1, bh2, bh3, bl0, bl1, bl2, bl3;
        ldsm_x4t(bh0, bh1, bh2, bh3, b_base + ntp * 32);
        ldsm_x4t(bl0, bl1, bl2, bl3, b_base + B0_BYTES + ntp * 32);
        mma_bf16(acc[2 * ntp + 0], ah, bh0, bh1);
        mma_bf16(acc[2 * ntp + 1], ah, bh2, bh3);
        mma_bf16(acc[2 * ntp + 0], ah, bl0, bl1);
        mma_bf16(acc[2 * ntp + 1], ah, bl2, bl3);
        mma_bf16(acc[2 * ntp + 0], al, bh0, bh1);
        mma_bf16(acc[2 * ntp + 1], al, bh2, bh3);
    }

    // epilogue: add bc, write
    int r0 = row0 + w * 16 + (lane >> 2);
    int r1 = r0 + 8;
    int cb = (lane & 3) * 2;
    #pragma unroll
    for (int nt = 0; nt < 16; nt++) {
        float2 bcv = *(const float2*)&g_bc[nt * 8 + cb];
        if (r0 < N_NODES)
            *(float2*)&g_m[(size_t)r0 * HID + nt * 8 + cb] =
                make_float2(acc[nt][0] + bcv.x, acc[nt][1] + bcv.y);
        if (r1 < N_NODES)
            *(float2*)&g_m[(size_t)r1 * HID + nt * 8 + cb] =
                make_float2(acc[nt][2] + bcv.x, acc[nt][3] + bcv.y);
    }
}

// ---------------- mma.sync bf16 3-term GEMM: g_m = h(sel) @ W ----------------
__global__ void __launch_bounds__(256, 1) k_gemm_mma(int hsel, const float* __restrict__ W) {
    extern __shared__ char sm[];
    int tid = threadIdx.x;
    const float* __restrict__ h = buf_sel(hsel);
    int row0 = blockIdx.x * TILE_M;

    #pragma unroll
    for (int j = 0; j < 16; j++) {
        int f = tid + 256 * j;
        int r = f >> 5, kg = f & 31;
        int row = row0 + r;
        if (row >= N_NODES) row = N_NODES - 1;
        float4 v = *(const float4*)&h[(size_t)row * HID + kg * 4];
        float h0, l0, h1, l1, h2, l2, h3, l3;
        bfsplit(v.x, h0, l0); bfsplit(v.y, h1, l1);
        bfsplit(v.z, h2, l2); bfsplit(v.w, h3, l3);
        uint2 hp, lp;
        hp.x = bfpack(h0, h1); hp.y = bfpack(h2, h3);
        lp.x = bfpack(l0, l1); lp.y = bfpack(l2, l3);
        *(uint2*)(sm + OFF_AHI + r * PADB + kg * 8) = hp;
        *(uint2*)(sm + OFF_ALO + r * PADB + kg * 8) = lp;
    }
    #pragma unroll
    for (int j = 0; j < 16; j++) {
        int f = tid + 256 * j;
        int k = f >> 5, ng = f & 31;
        float4 v = *(const float4*)&W[(size_t)k * HID + ng * 4];
        float h0, l0, h1, l1, h2, l2, h3, l3;
        bfsplit(v.x, h0, l0); bfsplit(v.y, h1, l1);
        bfsplit(v.z, h2, l2); bfsplit(v.w, h3, l3);
        uint2 hp, lp;
        hp.x = bfpack(h0, h1); hp.y = bfpack(h2, h3);
        lp.x = bfpack(l0, l1); lp.y = bfpack(l2, l3);
        *(uint2*)(sm + OFF_BHI + k * PADB + ng * 8) = hp;
        *(uint2*)(sm + OFF_BLO + k * PADB + ng * 8) = lp;
    }
    __syncthreads();

    int lane = tid & 31, w = tid >> 5;
    uint32_t sbase = smem_u32(sm);

    float acc[16][4];
    #pragma unroll
    for (int t = 0; t < 16; t++)
        #pragma unroll
        for (int i = 0; i < 4; i++) acc[t][i] = 0.f;

    uint32_t a_row_addr = sbase + OFF_AHI + (w * 16 + (lane & 15)) * PADB + (lane >> 4) * 16;

    #pragma unroll
    for (int ks = 0; ks < 8; ks++) {
        uint32_t ah[4], al[4];
        uint32_t aaddr = a_row_addr + ks * 32;
        ldsm_x4(ah[0], ah[1], ah[2], ah[3], aaddr);
        ldsm_x4(al[0], al[1], al[2], al[3], aaddr + TILE_BYTES);

        uint32_t b_base = sbase + OFF_BHI + (ks * 16 + (lane & 15)) * PADB + (lane >> 4) * 16;
        #pragma unroll
        for (int ntp = 0; ntp < 8; ntp++) {
            uint32_t bh0, bh1, bh2, bh3, bl0, bl1, bl2, bl3;
            ldsm_x4t(bh0, bh1, bh2, bh3, b_base + ntp * 32);
            ldsm_x4t(bl0, bl1, bl2, bl3, b_base + TILE_BYTES + ntp * 32);
            mma_bf16(acc[2 * ntp + 0], ah, bh0, bh1);
            mma_bf16(acc[2 * ntp + 1], ah, bh2, bh3);
            mma_bf16(acc[2 * ntp + 0], ah, bl0, bl1);
            mma_bf16(acc[2 * ntp + 1], ah, bl2, bl3);
            mma_bf16(acc[2 * ntp + 0], al, bh0, bh1);
            mma_bf16(acc[2 * ntp + 1], al, bh2, bh3);
        }
    }

    int r0 = row0 + w * 16 + (lane >> 2);
    int r1 = r0 + 8;
    int cb = (lane & 3) * 2;
    #pragma unroll
    for (int nt = 0; nt < 16; nt++) {
        if (r0 < N_NODES)
            *(float2*)&g_m[(size_t)r0 * HID + nt * 8 + cb] =
                make_float2(acc[nt][0], acc[nt][1]);
        if (r1 < N_NODES)
            *(float2*)&g_m[(size_t)r1 * HID + nt * 8 + cb] =
                make_float2(acc[nt][2], acc[nt][3]);
    }
}

// -------- aggregation + bias + LayerNorm + ReLU + residual --------
__global__ void k_agg(const float* __restrict__ bconv,
                      const float* __restrict__ gamma,
                      const float* __restrict__ beta,
                      int prevsel, int outsel, float* out_ext) {
    int warp = (blockIdx.x * blockDim.x + threadIdx.x) >> 5;
    int lane = threadIdx.x & 31;
    if (warp >= N_NODES) return;
    int i = warp;

    float di = g_dis[i];
    float sc = di * di;
    float4 acc = *(const float4*)&g_m[(size_t)i * HID + lane * 4];
    acc.x *= sc; acc.y *= sc; acc.z *= sc; acc.w *= sc;

    int e0 = g_rowptr[i], e1 = g_rowptr[i + 1];
    int e = e0;
    for (; e + 2 <= e1; e += 2) {
        int s0 = g_col[e], s1 = g_col[e + 1];
        float w0 = g_w[e], w1 = g_w[e + 1];
        float4 m0 = *(const float4*)&g_m[(size_t)s0 * HID + lane * 4];
        float4 m1 = *(const float4*)&g_m[(size_t)s1 * HID + lane * 4];
        acc.x += m0.x * w0 + m1.x * w1;
        acc.y += m0.y * w0 + m1.y * w1;
        acc.z += m0.z * w0 + m1.z * w1;
        acc.w += m0.w * w0 + m1.w * w1;
    }
    if (e < e1) {
        int s0 = g_col[e];
        float w0 = g_w[e];
        float4 m0 = *(const float4*)&g_m[(size_t)s0 * HID + lane * 4];
        acc.x += m0.x * w0;
        acc.y += m0.y * w0;
        acc.z += m0.z * w0;
        acc.w += m0.w * w0;
    }

    float4 bv = *(const float4*)&bconv[lane * 4];
    acc.x += bv.x; acc.y += bv.y; acc.z += bv.z; acc.w += bv.w;

    float sum = acc.x + acc.y + acc.z + acc.w;
    float sumsq = acc.x * acc.x + acc.y * acc.y + acc.z * acc.z + acc.w * acc.w;
    #pragma unroll
    for (int o = 16; o >= 1; o >>= 1) {
        sum += __shfl_xor_sync(0xFFFFFFFFu, sum, o);
        sumsq += __shfl_xor_sync(0xFFFFFFFFu, sumsq, o);
    }
    float mu = sum * (1.0f / HID);
    float var = sumsq * (1.0f / HID) - mu * mu;
    float inv = rsqrtf(var + LN_EPS);

    float4 gv = *(const float4*)&gamma[lane * 4];
    float4 btv = *(const float4*)&beta[lane * 4];
    float4 o4;
    o4.x = fmaxf((acc.x - mu) * inv * gv.x + btv.x, 0.f);
    o4.y = fmaxf((acc.y - mu) * inv * gv.y + btv.y, 0.f);
    o4.z = fmaxf((acc.z - mu) * inv * gv.z + btv.z, 0.f);
    o4.w = fmaxf((acc.w - mu) * inv * gv.w + btv.w, 0.f);

    if (prevsel >= 0) {
        const float* hprev = buf_sel(prevsel);
        float4 hp = *(const float4*)&hprev[(size_t)i * HID + lane * 4];
        o4.x += hp.x; o4.y += hp.y; o4.z += hp.z; o4.w += hp.w;
    }

    float* out = (outsel == 2) ? out_ext : buf_sel(outsel);
    *(float4*)&out[(size_t)i * HID + lane * 4] = o4;
}

// ---------------- launch ----------------
extern "C" void kernel_launch(void* const* d_in, const int* in_sizes, int n_in,
                              void* d_out, int out_size) {
    const float* x     = (const float*)d_in[0];
    const int*   ei_w  = (const int*)d_in[1];
    const float* Win   = (const float*)d_in[2];
    const float* bin   = (const float*)d_in[3];
    const float* Wconv = (const float*)d_in[4];
    const float* bconv = (const float*)d_in[5];
    const float* gamma = (const float*)d_in[6];
    const float* beta  = (const float*)d_in[7];
    float* out = (float*)d_out;

    cudaFuncSetAttribute(k_gemm_mma, cudaFuncAttributeMaxDynamicSharedMemorySize, SM_GEMM);

    const int NODE_BLOCKS = (N_NODES + 255) / 256;
    const int EDGE_BLOCKS = (N_EDGES + 255) / 256;
    const int SCAN_BLOCKS = (N_NODES + 1023) / 1024;

    k_combine<<<1, HID>>>(Win, bin, Wconv + 0 * HID * HID);   // 0
    k_detect<<<1, 32>>>(ei_w);                                 // 1
    k_zero_cnt<<<NODE_BLOCKS, 256>>>();                        // 2
    k_mma0<<<GEMM_TILES, 256>>>(x);                            // 3 <- profiled slot
    k_count<<<EDGE_BLOCKS, 256>>>(ei_w);                       // 4
    k_scan1<<<SCAN_BLOCKS, 1024>>>();                          // 5
    k_scan2<<<1, 32>>>(SCAN_BLOCKS);                           // 6
    k_scan3<<<NODE_BLOCKS, 256>>>();                           // 7 (deg fused)
    k_scatter<<<EDGE_BLOCKS, 256>>>(ei_w);                     // 8

    const int AGG_BLOCKS = (N_NODES * 32 + 255) / 256;

    // layer 0 agg: -> h1 (no residual)
    k_agg<<<AGG_BLOCKS, 256>>>(bconv + 0 * HID, gamma + 0 * HID, beta + 0 * HID,
                               -1, 1, nullptr);
    // layer 1: h1 -> h0 (+ residual h1)
    k_gemm_mma<<<GEMM_TILES, 256, SM_GEMM>>>(1, Wconv + 1 * HID * HID);
    k_agg<<<AGG_BLOCKS, 256>>>(bconv + 1 * HID, gamma + 1 * HID, beta + 1 * HID,
                               1, 0, nullptr);
    // layer 2: h0 -> out (+ residual h0)
    k_gemm_mma<<<GEMM_TILES, 256, SM_GEMM>>>(0, Wconv + 2 * HID * HID);
    k_agg<<<AGG_BLOCKS, 256>>>(bconv + 2 * HID, gamma + 2 * HID, beta + 2 * HID,
                               0, 2, out);
}

// round 15
// speedup vs baseline: 1.5355x; 1.0556x over previous
#include <cuda_runtime.h>
#include <cuda_bf16.h>
#include <cstdint>

#define N_NODES 100000
#define N_EDGES 1600000
#define IN_DIM  16
#define HID     128
#define LN_EPS  1e-5f

#define TILE_M  64
#define GEMM_TILES ((N_NODES + TILE_M - 1) / TILE_M)   // 1563

// SMEM layout for k_gemm_mma: A tiles 64x128, B tiles 128x128 (bf16, rows padded 272B)
#define PADB    272
#define A_BYTES (64 * PADB)                // 17408
#define B_BYTES (128 * PADB)               // 34816
#define OFF_AHI 0
#define OFF_ALO A_BYTES
#define OFF_BHI (2 * A_BYTES)
#define OFF_BLO (2 * A_BYTES + B_BYTES)
#define SM_GEMM (2 * A_BYTES + 2 * B_BYTES)  // 104448

// k_mma0 (K=16): A 64x16 rows padded 48B, B 16x128 rows padded 272B
#define PADA0   48
#define A0_BYTES (64 * PADA0)              // 3072
#define B0_BYTES (16 * PADB)               // 4352

// ---------------- scratch (no allocation allowed) ----------------
__device__ float g_dis[N_NODES];
__device__ int   g_cnt[N_NODES];
__device__ int   g_rowptr[N_NODES + 1];
__device__ int   g_cursor[N_NODES];
__device__ int   g_partial[128];
__device__ int   g_col[N_EDGES];
__device__ float g_w[N_EDGES];
__device__ float g_m[(size_t)N_NODES * HID];
__device__ float g_h0[(size_t)N_NODES * HID];
__device__ float g_h1[(size_t)N_NODES * HID];
__device__ float g_Wc[IN_DIM * HID];
__device__ float g_bc[HID];
__device__ int   g_stride;

__device__ __forceinline__ float* buf_sel(int s) {
    return (s == 0) ? g_h0 : g_h1;
}

// ---------------- helpers ----------------
__device__ __forceinline__ uint32_t smem_u32(const void* p) {
    uint32_t a;
    asm("{ .reg .u64 t; cvta.to.shared.u64 t, %1; cvt.u32.u64 %0, t; }" : "=r"(a) : "l"(p));
    return a;
}
__device__ __forceinline__ uint32_t bfpack(float a, float b) {
    __nv_bfloat162 t = __floats2bfloat162_rn(a, b);
    return *reinterpret_cast<uint32_t*>(&t);
}
__device__ __forceinline__ void bfsplit(float v, float& hi, float& lo) {
    __nv_bfloat16 h = __float2bfloat16(v);
    hi = __bfloat162float(h);
    lo = v - hi;
}
__device__ __forceinline__ void ldsm_x4(uint32_t& r0, uint32_t& r1, uint32_t& r2,
                                        uint32_t& r3, uint32_t addr) {
    asm volatile("ldmatrix.sync.aligned.m8n8.x4.shared.b16 {%0,%1,%2,%3}, [%4];"
                 : "=r"(r0), "=r"(r1), "=r"(r2), "=r"(r3) : "r"(addr));
}
__device__ __forceinline__ void ldsm_x4t(uint32_t& r0, uint32_t& r1, uint32_t& r2,
                                         uint32_t& r3, uint32_t addr) {
    asm volatile("ldmatrix.sync.aligned.m8n8.x4.trans.shared.b16 {%0,%1,%2,%3}, [%4];"
                 : "=r"(r0), "=r"(r1), "=r"(r2), "=r"(r3) : "r"(addr));
}
__device__ __forceinline__ void mma_bf16(float* d, const uint32_t* a,
                                         uint32_t b0, uint32_t b1) {
    asm volatile(
        "mma.sync.aligned.m16n8k16.row.col.f32.bf16.bf16.f32 "
        "{%0,%1,%2,%3}, {%4,%5,%6,%7}, {%8,%9}, {%0,%1,%2,%3};"
        : "+f"(d[0]), "+f"(d[1]), "+f"(d[2]), "+f"(d[3])
        : "r"(a[0]), "r"(a[1]), "r"(a[2]), "r"(a[3]), "r"(b0), "r"(b1));
}

// ---------------- detect + zero counts (fused) ----------------
__global__ void k_detect(const int* __restrict__ ei_w) {
    int i = blockIdx.x * blockDim.x + threadIdx.x;
    if (i < N_NODES) g_cnt[i] = 0;
    if (blockIdx.x == 0 && threadIdx.x == 0) {
        bool all_zero = true;
        for (int j = 0; j < 32; j++)
            if (ei_w[2 * j + 1] != 0) { all_zero = false; break; }
        g_stride = all_zero ? 2 : 1;
    }
}

__global__ void k_count(const int* __restrict__ ei_w) {
    int e = blockIdx.x * blockDim.x + threadIdx.x;
    if (e >= N_EDGES) return;
    int st = g_stride;
    int d = ei_w[(size_t)N_EDGES * st + (size_t)e * st];
    if ((unsigned)d < N_NODES) atomicAdd(&g_cnt[d], 1);
}

__global__ void k_scan1() {
    __shared__ int warp_sums[32];
    int tid = threadIdx.x;
    int gid = blockIdx.x * 1024 + tid;
    int v = (gid < N_NODES) ? g_cnt[gid] : 0;
    int lane = tid & 31, wid = tid >> 5;
    int x = v;
    #pragma unroll
    for (int o = 1; o < 32; o <<= 1) {
        int y = __shfl_up_sync(0xFFFFFFFFu, x, o);
        if (lane >= o) x += y;
    }
    if (lane == 31) warp_sums[wid] = x;
    __syncthreads();
    if (wid == 0) {
        int s = warp_sums[lane];
        #pragma unroll
        for (int o = 1; o < 32; o <<= 1) {
            int y = __shfl_up_sync(0xFFFFFFFFu, s, o);
            if (lane >= o) s += y;
        }
        warp_sums[lane] = s;
    }
    __syncthreads();
    int base = (wid > 0) ? warp_sums[wid - 1] : 0;
    if (gid < N_NODES) g_rowptr[gid] = base + x - v;
    if (tid == 1023) g_partial[blockIdx.x] = base + x;
}

__global__ void k_scan2(int nblocks) {
    if (threadIdx.x == 0 && blockIdx.x == 0) {
        int acc = 0;
        for (int i = 0; i < nblocks; i++) {
            int t = g_partial[i];
            g_partial[i] = acc;
            acc += t;
        }
    }
}

// scan3 + deg fused (g_cnt still valid here)
__global__ void k_scan3() {
    int i = blockIdx.x * blockDim.x + threadIdx.x;
    if (i < N_NODES) {
        int rp = g_rowptr[i] + g_partial[i >> 10];
        g_rowptr[i] = rp;
        g_cursor[i] = rp;
        g_dis[i] = rsqrtf((float)(g_cnt[i] + 1));
    }
    if (i == 0) g_rowptr[N_NODES] = N_EDGES;
}

__global__ void k_scatter(const int* __restrict__ ei_w) {
    int e = blockIdx.x * blockDim.x + threadIdx.x;
    if (e >= N_EDGES) return;
    int st = g_stride;
    int s = ei_w[(size_t)e * st];
    int d = ei_w[(size_t)N_EDGES * st + (size_t)e * st];
    if ((unsigned)s >= N_NODES || (unsigned)d >= N_NODES) return;
    int pos = atomicAdd(&g_cursor[d], 1);
    if ((unsigned)pos < N_EDGES) {
        g_col[pos] = s;
        g_w[pos] = g_dis[s] * g_dis[d];
    }
}

// ---------------- combined weight: Wc = W_in @ W0, bc = b_in @ W0 ----------------
__global__ void k_combine(const float* __restrict__ Win,
                          const float* __restrict__ bin,
                          const float* __restrict__ W0) {
    int c = threadIdx.x;
    float acc[IN_DIM];
    #pragma unroll
    for (int k = 0; k < IN_DIM; k++) acc[k] = 0.f;
    float bacc = 0.f;
    for (int j = 0; j < HID; j++) {
        float w = W0[j * HID + c];
        bacc += bin[j] * w;
        #pragma unroll
        for (int k = 0; k < IN_DIM; k++) acc[k] += Win[k * HID + j] * w;
    }
    #pragma unroll
    for (int k = 0; k < IN_DIM; k++) g_Wc[k * HID + c] = acc[k];
    g_bc[c] = bacc;
}

// -------- layer-0: g_m = x @ Wc + bc (K=16), tensor cores, TILE_M=64 --------
__global__ void __launch_bounds__(256) k_mma0(const float* __restrict__ x) {
    __shared__ char sm[2 * A0_BYTES + 2 * B0_BYTES];
    const int A_HI = 0, A_LO = A0_BYTES;
    const int B_HI = 2 * A0_BYTES, B_LO = 2 * A0_BYTES + B0_BYTES;
    int tid = threadIdx.x;
    int row0 = blockIdx.x * TILE_M;

    // A fill: 64 rows x 4 float4 = 256 -> 1 per thread
    {
        int r = tid >> 2, g = tid & 3;
        int row = row0 + r;
        if (row >= N_NODES) row = N_NODES - 1;
        float4 v = *(const float4*)&x[(size_t)row * IN_DIM + g * 4];
        float h0, l0, h1, l1, h2, l2, h3, l3;
        bfsplit(v.x, h0, l0); bfsplit(v.y, h1, l1);
        bfsplit(v.z, h2, l2); bfsplit(v.w, h3, l3);
        uint2 hp, lp;
        hp.x = bfpack(h0, h1); hp.y = bfpack(h2, h3);
        lp.x = bfpack(l0, l1); lp.y = bfpack(l2, l3);
        *(uint2*)(sm + A_HI + r * PADA0 + g * 8) = hp;
        *(uint2*)(sm + A_LO + r * PADA0 + g * 8) = lp;
    }
    // B fill: 16 x 32 float4 = 512 -> 2 per thread
    #pragma unroll
    for (int j = 0; j < 2; j++) {
        int f = tid + 256 * j;
        int k = f >> 5, ng = f & 31;
        float4 v = *(const float4*)&g_Wc[k * HID + ng * 4];
        float h0, l0, h1, l1, h2, l2, h3, l3;
        bfsplit(v.x, h0, l0); bfsplit(v.y, h1, l1);
        bfsplit(v.z, h2, l2); bfsplit(v.w, h3, l3);
        uint2 hp, lp;
        hp.x = bfpack(h0, h1); hp.y = bfpack(h2, h3);
        lp.x = bfpack(l0, l1); lp.y = bfpack(l2, l3);
        *(uint2*)(sm + B_HI + k * PADB + ng * 8) = hp;
        *(uint2*)(sm + B_LO + k * PADB + ng * 8) = lp;
    }
    __syncthreads();

    int lane = tid & 31, w = tid >> 5;
    int rg = w >> 1, ch = w & 1;          // row-group 0..3, col-half 0..1
    uint32_t sbase = smem_u32(sm);

    float acc[8][4];
    #pragma unroll
    for (int t = 0; t < 8; t++)
        #pragma unroll
        for (int i = 0; i < 4; i++) acc[t][i] = 0.f;

    uint32_t aaddr = sbase + A_HI + (rg * 16 + (lane & 15)) * PADA0 + (lane >> 4) * 16;
    uint32_t ah[4], al[4];
    ldsm_x4(ah[0], ah[1], ah[2], ah[3], aaddr);
    ldsm_x4(al[0], al[1], al[2], al[3], aaddr + A0_BYTES);

    uint32_t b_base = sbase + B_HI + (lane & 15) * PADB + (lane >> 4) * 16 + ch * 128;
    #pragma unroll
    for (int ntp = 0; ntp < 4; ntp++) {
        uint32_t bh0, bh1, bh2, bh3, bl0, bl1, bl2, bl3;
        ldsm_x4t(bh0, bh1, bh2, bh3, b_base + ntp * 32);
        ldsm_x4t(bl0, bl1, bl2, bl3, b_base + B0_BYTES + ntp * 32);
        mma_bf16(acc[2 * ntp + 0], ah, bh0, bh1);
        mma_bf16(acc[2 * ntp + 1], ah, bh2, bh3);
        mma_bf16(acc[2 * ntp + 0], ah, bl0, bl1);
        mma_bf16(acc[2 * ntp + 1], ah, bl2, bl3);
        mma_bf16(acc[2 * ntp + 0], al, bh0, bh1);
        mma_bf16(acc[2 * ntp + 1], al, bh2, bh3);
    }

    int r0 = row0 + rg * 16 + (lane >> 2);
    int r1 = r0 + 8;
    int cb = ch * 64 + (lane & 3) * 2;
    #pragma unroll
    for (int nt = 0; nt < 8; nt++) {
        float2 bcv = *(const float2*)&g_bc[cb + nt * 8];
        if (r0 < N_NODES)
            *(float2*)&g_m[(size_t)r0 * HID + cb + nt * 8] =
                make_float2(acc[nt][0] + bcv.x, acc[nt][1] + bcv.y);
        if (r1 < N_NODES)
            *(float2*)&g_m[(size_t)r1 * HID + cb + nt * 8] =
                make_float2(acc[nt][2] + bcv.x, acc[nt][3] + bcv.y);
    }
}

// ---------------- mma.sync bf16 3-term GEMM, TILE_M=64: g_m = h(sel) @ W ----------------
__global__ void __launch_bounds__(256) k_gemm_mma(int hsel, const float* __restrict__ W) {
    extern __shared__ char sm[];
    int tid = threadIdx.x;
    const float* __restrict__ h = buf_sel(hsel);
    int row0 = blockIdx.x * TILE_M;

    // A fill: 64 rows x 32 float4 = 2048 -> 8 per thread
    #pragma unroll
    for (int j = 0; j < 8; j++) {
        int f = tid + 256 * j;
        int r = f >> 5, kg = f & 31;
        int row = row0 + r;
        if (row >= N_NODES) row = N_NODES - 1;
        float4 v = *(const float4*)&h[(size_t)row * HID + kg * 4];
        float h0, l0, h1, l1, h2, l2, h3, l3;
        bfsplit(v.x, h0, l0); bfsplit(v.y, h1, l1);
        bfsplit(v.z, h2, l2); bfsplit(v.w, h3, l3);
        uint2 hp, lp;
        hp.x = bfpack(h0, h1); hp.y = bfpack(h2, h3);
        lp.x = bfpack(l0, l1); lp.y = bfpack(l2, l3);
        *(uint2*)(sm + OFF_AHI + r * PADB + kg * 8) = hp;
        *(uint2*)(sm + OFF_ALO + r * PADB + kg * 8) = lp;
    }
    // B fill: 128 k-rows x 32 float4 = 4096 -> 16 per thread
    #pragma unroll
    for (int j = 0; j < 16; j++) {
        int f = tid + 256 * j;
        int k = f >> 5, ng = f & 31;
        float4 v = *(const float4*)&W[(size_t)k * HID + ng * 4];
        float h0, l0, h1, l1, h2, l2, h3, l3;
        bfsplit(v.x, h0, l0); bfsplit(v.y, h1, l1);
        bfsplit(v.z, h2, l2); bfsplit(v.w, h3, l3);
        uint2 hp, lp;
        hp.x = bfpack(h0, h1); hp.y = bfpack(h2, h3);
        lp.x = bfpack(l0, l1); lp.y = bfpack(l2, l3);
        *(uint2*)(sm + OFF_BHI + k * PADB + ng * 8) = hp;
        *(uint2*)(sm + OFF_BLO + k * PADB + ng * 8) = lp;
    }
    __syncthreads();

    int lane = tid & 31, w = tid >> 5;
    int rg = w >> 1, ch = w & 1;
    uint32_t sbase = smem_u32(sm);

    float acc[8][4];
    #pragma unroll
    for (int t = 0; t < 8; t++)
        #pragma unroll
        for (int i = 0; i < 4; i++) acc[t][i] = 0.f;

    uint32_t a_row_addr = sbase + OFF_AHI + (rg * 16 + (lane & 15)) * PADB + (lane >> 4) * 16;

    #pragma unroll
    for (int ks = 0; ks < 8; ks++) {
        uint32_t ah[4], al[4];
        uint32_t aaddr = a_row_addr + ks * 32;
        ldsm_x4(ah[0], ah[1], ah[2], ah[3], aaddr);
        ldsm_x4(al[0], al[1], al[2], al[3], aaddr + A_BYTES);

        uint32_t b_base = sbase + OFF_BHI + (ks * 16 + (lane & 15)) * PADB +
                          (lane >> 4) * 16 + ch * 128;
        #pragma unroll
        for (int ntp = 0; ntp < 4; ntp++) {
            uint32_t bh0, bh1, bh2, bh3, bl0, bl1, bl2, bl3;
            ldsm_x4t(bh0, bh1, bh2, bh3, b_base + ntp * 32);
            ldsm_x4t(bl0, bl1, bl2, bl3, b_base + B_BYTES + ntp * 32);
            mma_bf16(acc[2 * ntp + 0], ah, bh0, bh1);
            mma_bf16(acc[2 * ntp + 1], ah, bh2, bh3);
            mma_bf16(acc[2 * ntp + 0], ah, bl0, bl1);
            mma_bf16(acc[2 * ntp + 1], ah, bl2, bl3);
            mma_bf16(acc[2 * ntp + 0], al, bh0, bh1);
            mma_bf16(acc[2 * ntp + 1], al, bh2, bh3);
        }
    }

    int r0 = row0 + rg * 16 + (lane >> 2);
    int r1 = r0 + 8;
    int cb = ch * 64 + (lane & 3) * 2;
    #pragma unroll
    for (int nt = 0; nt < 8; nt++) {
        if (r0 < N_NODES)
            *(float2*)&g_m[(size_t)r0 * HID + cb + nt * 8] =
                make_float2(acc[nt][0], acc[nt][1]);
        if (r1 < N_NODES)
            *(float2*)&g_m[(size_t)r1 * HID + cb + nt * 8] =
                make_float2(acc[nt][2], acc[nt][3]);
    }
}

// -------- aggregation + bias + LayerNorm + ReLU + residual --------
__global__ void k_agg(const float* __restrict__ bconv,
                      const float* __restrict__ gamma,
                      const float* __restrict__ beta,
                      int prevsel, int outsel, float* out_ext) {
    int warp = (blockIdx.x * blockDim.x + threadIdx.x) >> 5;
    int lane = threadIdx.x & 31;
    if (warp >= N_NODES) return;
    int i = warp;

    float di = g_dis[i];
    float sc = di * di;
    float4 acc = *(const float4*)&g_m[(size_t)i * HID + lane * 4];
    acc.x *= sc; acc.y *= sc; acc.z *= sc; acc.w *= sc;

    int e0 = g_rowptr[i], e1 = g_rowptr[i + 1];
    int e = e0;
    for (; e + 2 <= e1; e += 2) {
        int s0 = g_col[e], s1 = g_col[e + 1];
        float w0 = g_w[e], w1 = g_w[e + 1];
        float4 m0 = *(const float4*)&g_m[(size_t)s0 * HID + lane * 4];
        float4 m1 = *(const float4*)&g_m[(size_t)s1 * HID + lane * 4];
        acc.x += m0.x * w0 + m1.x * w1;
        acc.y += m0.y * w0 + m1.y * w1;
        acc.z += m0.z * w0 + m1.z * w1;
        acc.w += m0.w * w0 + m1.w * w1;
    }
    if (e < e1) {
        int s0 = g_col[e];
        float w0 = g_w[e];
        float4 m0 = *(const float4*)&g_m[(size_t)s0 * HID + lane * 4];
        acc.x += m0.x * w0;
        acc.y += m0.y * w0;
        acc.z += m0.z * w0;
        acc.w += m0.w * w0;
    }

    float4 bv = *(const float4*)&bconv[lane * 4];
    acc.x += bv.x; acc.y += bv.y; acc.z += bv.z; acc.w += bv.w;

    float sum = acc.x + acc.y + acc.z + acc.w;
    float sumsq = acc.x * acc.x + acc.y * acc.y + acc.z * acc.z + acc.w * acc.w;
    #pragma unroll
    for (int o = 16; o >= 1; o >>= 1) {
        sum += __shfl_xor_sync(0xFFFFFFFFu, sum, o);
        sumsq += __shfl_xor_sync(0xFFFFFFFFu, sumsq, o);
    }
    float mu = sum * (1.0f / HID);
    float var = sumsq * (1.0f / HID) - mu * mu;
    float inv = rsqrtf(var + LN_EPS);

    float4 gv = *(const float4*)&gamma[lane * 4];
    float4 btv = *(const float4*)&beta[lane * 4];
    float4 o4;
    o4.x = fmaxf((acc.x - mu) * inv * gv.x + btv.x, 0.f);
    o4.y = fmaxf((acc.y - mu) * inv * gv.y + btv.y, 0.f);
    o4.z = fmaxf((acc.z - mu) * inv * gv.z + btv.z, 0.f);
    o4.w = fmaxf((acc.w - mu) * inv * gv.w + btv.w, 0.f);

    if (prevsel >= 0) {
        const float* hprev = buf_sel(prevsel);
        float4 hp = *(const float4*)&hprev[(size_t)i * HID + lane * 4];
        o4.x += hp.x; o4.y += hp.y; o4.z += hp.z; o4.w += hp.w;
    }

    float* out = (outsel == 2) ? out_ext : buf_sel(outsel);
    *(float4*)&out[(size_t)i * HID + lane * 4] = o4;
}

// ---------------- launch ----------------
extern "C" void kernel_launch(void* const* d_in, const int* in_sizes, int n_in,
                              void* d_out, int out_size) {
    const float* x     = (const float*)d_in[0];
    const int*   ei_w  = (const int*)d_in[1];
    const float* Win   = (const float*)d_in[2];
    const float* bin   = (const float*)d_in[3];
    const float* Wconv = (const float*)d_in[4];
    const float* bconv = (const float*)d_in[5];
    const float* gamma = (const float*)d_in[6];
    const float* beta  = (const float*)d_in[7];
    float* out = (float*)d_out;

    cudaFuncSetAttribute(k_gemm_mma, cudaFuncAttributeMaxDynamicSharedMemorySize, SM_GEMM);

    const int NODE_BLOCKS = (N_NODES + 255) / 256;
    const int EDGE_BLOCKS = (N_EDGES + 255) / 256;
    const int SCAN_BLOCKS = (N_NODES + 1023) / 1024;

    k_combine<<<1, HID>>>(Win, bin, Wconv + 0 * HID * HID);   // 0
    k_detect<<<NODE_BLOCKS, 256>>>(ei_w);                      // 1 (zero fused)
    k_count<<<EDGE_BLOCKS, 256>>>(ei_w);                       // 2
    k_mma0<<<GEMM_TILES, 256>>>(x);                            // 3 <- profiled slot
    k_scan1<<<SCAN_BLOCKS, 1024>>>();                          // 4
    k_scan2<<<1, 32>>>(SCAN_BLOCKS);                           // 5
    k_scan3<<<NODE_BLOCKS, 256>>>();                           // 6 (deg fused)
    k_scatter<<<EDGE_BLOCKS, 256>>>(ei_w);                     // 7

    const int AGG_BLOCKS = (N_NODES * 32 + 255) / 256;

    // layer 0 agg: -> h1 (no residual)
    k_agg<<<AGG_BLOCKS, 256>>>(bconv + 0 * HID, gamma + 0 * HID, beta + 0 * HID,
                               -1, 1, nullptr);
    // layer 1: h1 -> h0 (+ residual h1)
    k_gemm_mma<<<GEMM_TILES, 256, SM_GEMM>>>(1, Wconv + 1 * HID * HID);
    k_agg<<<AGG_BLOCKS, 256>>>(bconv + 1 * HID, gamma + 1 * HID, beta + 1 * HID,
                               1, 0, nullptr);
    // layer 2: h0 -> out (+ residual h0)
    k_gemm_mma<<<GEMM_TILES, 256, SM_GEMM>>>(0, Wconv + 2 * HID * HID);
    k_agg<<<AGG_BLOCKS, 256>>>(bconv + 2 * HID, gamma + 2 * HID, beta + 2 * HID,
                               0, 2, out);
}